// round 9
// baseline (speedup 1.0000x reference)
#include <cuda_runtime.h>

// Problem constants
#define BATCH   256          // B_
#define NTOK    256          // N tokens per window
#define DIM     192
#define HEADS   6
#define HD      32           // head dim
#define NW      64           // number of windows (mask slices)
#define ROWS    (BATCH*NTOK) // 65536 GEMM rows
#define SCALE   0.17677669529663687f   // 32^-0.5

typedef unsigned int uint;

// ---------------------------------------------------------------------------
// tf32 mma helpers (m16n8k8; gr=lane>>2, tg=lane&3)
// ---------------------------------------------------------------------------
__device__ __forceinline__ uint to_tf32(float f) {
    uint u;
    asm("cvt.rna.tf32.f32 %0, %1;" : "=r"(u) : "f"(f));
    return u;
}
__device__ __forceinline__ void mma8(float4& c, uint4 a, uint2 b) {
    asm("mma.sync.aligned.m16n8k8.row.col.f32.tf32.tf32.f32 "
        "{%0,%1,%2,%3},{%4,%5,%6,%7},{%8,%9},{%0,%1,%2,%3};"
        : "+f"(c.x), "+f"(c.y), "+f"(c.z), "+f"(c.w)
        : "r"(a.x), "r"(a.y), "r"(a.z), "r"(a.w), "r"(b.x), "r"(b.y));
}

// ---------------------------------------------------------------------------
// Scratch (device globals — no runtime allocation allowed)
// ---------------------------------------------------------------------------
__device__ float g_q[BATCH*HEADS*NTOK*HD];     // q pre-scaled
__device__ float g_k[BATCH*HEADS*NTOK*HD];
__device__ float g_v[BATCH*HEADS*NTOK*HD];
__device__ float g_att[ROWS*DIM];              // attention output rows
__device__ float g_bias[HEADS*NTOK*NTOK];      // gathered bias [h][n][m]

// ---------------------------------------------------------------------------
// Prep: bias gather [h][n][m] (1.5MB, L2-resident during attention)
// ---------------------------------------------------------------------------
__global__ void bias_gather_kernel(const float* __restrict__ table,
                                   const int* __restrict__ rel) {
    int idx = blockIdx.x * 256 + threadIdx.x;   // h*65536 + n*256 + m
    int m = idx & 255;
    int n = (idx >> 8) & 255;
    int h = idx >> 16;
    g_bias[idx] = table[rel[(n << 8) + m] * HEADS + h];
}

// ---------------------------------------------------------------------------
// tf32 GEMM core, CTA tile 128x192, 512 threads / 16 warps as 4(M) x 4(N),
// warp tile 32x48. Double-buffered smem, register-prefetched global loads.
// Swizzle: As[row][k ^ ((row&7)<<2)], Bs[k][n ^ ((k&3)<<3)] (conflict-free).
// ---------------------------------------------------------------------------
__device__ __forceinline__ void ldgA(float4* aP, const float* src,
                                     int row_base, int ld, int kb, int t) {
#pragma unroll
    for (int i = 0; i < 2; i++) {
        int fid = t + i * 512;
        int row = fid >> 3;
        int c   = (fid & 7) * 4;
        aP[i] = *(const float4*)&src[(size_t)(row_base + row) * ld + kb + c];
    }
}
__device__ __forceinline__ void stsA(uint* As, const float4* aP, int t) {
#pragma unroll
    for (int i = 0; i < 2; i++) {
        int fid = t + i * 512;
        int row = fid >> 3;
        int c   = (fid & 7) * 4;
        uint4 u;
        u.x = to_tf32(aP[i].x); u.y = to_tf32(aP[i].y);
        u.z = to_tf32(aP[i].z); u.w = to_tf32(aP[i].w);
        *(uint4*)&As[row * 32 + (c ^ ((row & 7) << 2))] = u;
    }
}
__device__ __forceinline__ void ldgB(float4* bP, const float* src,
                                     int ldn, int kb, int cb, int t) {
#pragma unroll
    for (int i = 0; i < 3; i++) {
        int fid = t + i * 512;
        int k = fid / 48;
        int c = (fid - k * 48) * 4;
        bP[i] = *(const float4*)&src[(size_t)(kb + k) * ldn + cb + c];
    }
}
__device__ __forceinline__ void stsB(uint* Bs, const float4* bP, int t) {
#pragma unroll
    for (int i = 0; i < 3; i++) {
        int fid = t + i * 512;
        int k = fid / 48;
        int c = (fid - k * 48) * 4;
        uint4 u;
        u.x = to_tf32(bP[i].x); u.y = to_tf32(bP[i].y);
        u.z = to_tf32(bP[i].z); u.w = to_tf32(bP[i].w);
        *(uint4*)&Bs[k * 192 + (c ^ ((k & 3) << 3))] = u;
    }
}
__device__ __forceinline__ uint4 ldA(const uint* As, int mtb, int kt,
                                     int gr, int tg) {
    int r0 = mtb + gr;
    int s  = (r0 & 7) << 2;
    int k0 = (kt * 8 + tg) ^ s;
    int k1 = (kt * 8 + tg + 4) ^ s;
    uint4 a;
    a.x = As[r0 * 32 + k0];
    a.y = As[(r0 + 8) * 32 + k0];
    a.z = As[r0 * 32 + k1];
    a.w = As[(r0 + 8) * 32 + k1];
    return a;
}
__device__ __forceinline__ uint2 ldB(const uint* Bs, int ntb, int kt,
                                     int gr, int tg) {
    int col = (ntb + gr) ^ (tg << 3);
    int k0  = kt * 8 + tg;
    uint2 b;
    b.x = Bs[k0 * 192 + col];
    b.y = Bs[(k0 + 4) * 192 + col];
    return b;
}

#define GEMM_MAINLOOP(srcA, ldA_, srcW, ldW, cbW)                              \
    float4 aP[2]; float4 bP[3];                                                \
    ldgA(aP, srcA, rb, ldA_, 0, t);                                            \
    ldgB(bP, srcW, ldW, 0, cbW, t);                                            \
    stsA(As, aP, t);                                                           \
    stsB(Bs, bP, t);                                                           \
    _Pragma("unroll")                                                          \
    for (int i = 0; i < 6; i++) {                                              \
        __syncthreads();                                                       \
        if (i < 5) {                                                           \
            ldgA(aP, srcA, rb, ldA_, (i + 1) * 32, t);                         \
            ldgB(bP, srcW, ldW, (i + 1) * 32, cbW, t);                         \
        }                                                                      \
        const uint* Ac = As + (i & 1) * 4096;                                  \
        const uint* Bc = Bs + (i & 1) * 6144;                                  \
        _Pragma("unroll")                                                      \
        for (int kt = 0; kt < 4; kt++) {                                       \
            uint4 a[2];                                                        \
            _Pragma("unroll")                                                  \
            for (int mt = 0; mt < 2; mt++)                                     \
                a[mt] = ldA(Ac, wm * 32 + mt * 16, kt, gr, tg);                \
            _Pragma("unroll")                                                  \
            for (int nt = 0; nt < 6; nt++) {                                   \
                uint2 b = ldB(Bc, wn * 48 + nt * 8, kt, gr, tg);               \
                mma8(acc[0][nt], a[0], b);                                     \
                mma8(acc[1][nt], a[1], b);                                     \
            }                                                                  \
        }                                                                      \
        if (i < 5) {                                                           \
            stsA(As + ((i + 1) & 1) * 4096, aP, t);                            \
            stsB(Bs + ((i + 1) & 1) * 6144, bP, t);                            \
        }                                                                      \
    }

// QKV GEMM: block x = mat (0=Q,1=K,2=V): cols [mat*192, mat*192+192)
__global__ __launch_bounds__(512) void qkv_gemm_kernel(
    const float* __restrict__ X, const float* __restrict__ W,
    const float* __restrict__ bias) {
    extern __shared__ uint smg[];
    uint* As = smg;          // 2 x 4096
    uint* Bs = smg + 8192;   // 2 x 6144
    __shared__ float sBias[192];

    int t    = threadIdx.x;
    int lane = t & 31;
    int wid  = t >> 5;
    int wm   = wid >> 2;        // 0..3
    int wn   = wid & 3;         // 0..3
    int gr   = lane >> 2, tg = lane & 3;
    int mat  = blockIdx.x;
    int rb   = blockIdx.y * 128;
    int cb   = mat * 192;

    if (t < 192) sBias[t] = bias[cb + t];

    float4 acc[2][6];
#pragma unroll
    for (int i = 0; i < 2; i++)
#pragma unroll
        for (int j = 0; j < 6; j++) acc[i][j] = make_float4(0.f, 0.f, 0.f, 0.f);

    GEMM_MAINLOOP(X, DIM, W, 576, cb)

    float* dst = (mat == 0) ? g_q : (mat == 1) ? g_k : g_v;
    float sc = (mat == 0) ? SCALE : 1.f;
#pragma unroll
    for (int mt = 0; mt < 2; mt++) {
#pragma unroll
        for (int nt = 0; nt < 6; nt++) {
            float4 c = acc[mt][nt];
            int cl = wn * 48 + nt * 8 + 2 * tg;
            float b0 = sBias[cl], b1 = sBias[cl + 1];
            int h = cl >> 5, d = cl & 31;
            int row = rb + wm * 32 + mt * 16 + gr;
#pragma unroll
            for (int r = 0; r < 2; r++) {
                int rw = row + r * 8;
                int bb = rw >> 8, n = rw & 255;
                float v0 = ((r == 0) ? c.x : c.z) + b0;
                float v1 = ((r == 0) ? c.y : c.w) + b1;
                size_t off = ((size_t)(bb * HEADS + h) * NTOK + n) * HD + d;
                *(float2*)&dst[off] = make_float2(v0 * sc, v1 * sc);
            }
        }
    }
}

// Proj GEMM: out = g_att(65536x192) @ proj_w(192x192) + proj_b
__global__ __launch_bounds__(512) void proj_gemm_kernel(
    const float* __restrict__ W, const float* __restrict__ bias,
    float* __restrict__ out) {
    extern __shared__ uint smg[];
    uint* As = smg;
    uint* Bs = smg + 8192;
    __shared__ float sBias[192];

    int t    = threadIdx.x;
    int lane = t & 31;
    int wid  = t >> 5;
    int wm   = wid >> 2;
    int wn   = wid & 3;
    int gr   = lane >> 2, tg = lane & 3;
    int rb   = blockIdx.y * 128;

    if (t < 192) sBias[t] = bias[t];

    float4 acc[2][6];
#pragma unroll
    for (int i = 0; i < 2; i++)
#pragma unroll
        for (int j = 0; j < 6; j++) acc[i][j] = make_float4(0.f, 0.f, 0.f, 0.f);

    GEMM_MAINLOOP(g_att, DIM, W, DIM, 0)

#pragma unroll
    for (int mt = 0; mt < 2; mt++) {
#pragma unroll
        for (int nt = 0; nt < 6; nt++) {
            float4 c = acc[mt][nt];
            int cl = wn * 48 + nt * 8 + 2 * tg;
            float b0 = sBias[cl], b1 = sBias[cl + 1];
            int row0 = rb + wm * 32 + mt * 16 + gr;
            *(float2*)&out[(size_t)row0 * DIM + cl] =
                make_float2(c.x + b0, c.y + b1);
            *(float2*)&out[(size_t)(row0 + 8) * DIM + cl] =
                make_float2(c.z + b0, c.w + b1);
        }
    }
}

// ---------------------------------------------------------------------------
// Tensor-core attention (unchanged from round 8). One CTA per (b,h);
// 8 warps x 32 query rows; bias+mask staged per warp per chunk.
// ---------------------------------------------------------------------------
__global__ __launch_bounds__(256, 2) void attn_tc_kernel(
    const float* __restrict__ mask) {
    extern __shared__ uint sm[];
    uint* Ks = sm;           // 8192
    uint* Vs = sm + 8192;    // 8192
    uint* Pq = sm + 16384;   // 8192 (Q staging, then 8 x 1024 per-warp bufs)

    int h = blockIdx.x;
    int b = blockIdx.y;
    int w = b & (NW - 1);
    int t = threadIdx.x;
    int lane = t & 31;
    int wid = t >> 5;
    int gr = lane >> 2, tg = lane & 3;

    size_t base = ((size_t)(b * HEADS + h)) * (NTOK * HD);

#pragma unroll
    for (int i = 0; i < 8; i++) {
        int fid = t + i * 256;
        int key = fid >> 3;
        int c   = (fid & 7) * 4;
        float4 v = *(const float4*)&g_k[base + key * HD + c];
        int kt  = c >> 3;
        int reg = (c & 4) >> 2;
        int wb  = (((kt * 32 + (key >> 3)) * 32 + (key & 7) * 4) * 2) + reg;
        Ks[wb + 0] = to_tf32(v.x);
        Ks[wb + 2] = to_tf32(v.y);
        Ks[wb + 4] = to_tf32(v.z);
        Ks[wb + 6] = to_tf32(v.w);
    }
#pragma unroll
    for (int i = 0; i < 8; i++) {
        int fid = t + i * 256;
        int key = fid >> 3;
        int c   = (fid & 7) * 4;
        float4 v = *(const float4*)&g_v[base + key * HD + c];
        int nt  = c >> 3;
        int reg = (key & 4) >> 2;
        int wb  = ((((key >> 3) * 4 + nt) * 32 + (c & 7) * 4 + (key & 3)) * 2) + reg;
        Vs[wb + 0]  = to_tf32(v.x);
        Vs[wb + 8]  = to_tf32(v.y);
        Vs[wb + 16] = to_tf32(v.z);
        Vs[wb + 24] = to_tf32(v.w);
    }
#pragma unroll
    for (int i = 0; i < 8; i++) {
        int fid = t + i * 256;
        int row = fid >> 3;
        int c   = (fid & 7) * 4;
        float4 v = *(const float4*)&g_q[base + row * HD + c];
        int kt  = c >> 3;
        int reg = ((c & 4) >> 1) | ((row & 8) >> 3);
        int wb  = (((kt * 16 + (row >> 4)) * 32 + (row & 7) * 4) * 4) + reg;
        Pq[wb + 0]  = to_tf32(v.x);
        Pq[wb + 4]  = to_tf32(v.y);
        Pq[wb + 8]  = to_tf32(v.z);
        Pq[wb + 12] = to_tf32(v.w);
    }
    __syncthreads();

    uint4 qa[2][4];
#pragma unroll
    for (int mi = 0; mi < 2; mi++)
#pragma unroll
        for (int kt = 0; kt < 4; kt++)
            qa[mi][kt] = *(const uint4*)&Pq[((kt * 16 + wid * 2 + mi) * 32 + lane) * 4];
    __syncthreads();   // Pq now reusable as per-warp buffers

    uint* Ps = Pq + wid * 1024;
    float* Pf = (float*)Ps;
    int fl = (lane ^ ((lane >> 3) & 3)) * 4;

    float4 O[2][4];
#pragma unroll
    for (int mi = 0; mi < 2; mi++)
#pragma unroll
        for (int nt = 0; nt < 4; nt++) O[mi][nt] = make_float4(0.f, 0.f, 0.f, 0.f);
    float lsum[2][2] = {{0.f, 0.f}, {0.f, 0.f}};

    int qb = wid * 32;
    const float* Bb = g_bias + ((size_t)h << 16) + ((size_t)qb << 8);
    const float* Mb = mask   + ((size_t)w << 16) + ((size_t)qb << 8);
    int ldr = lane >> 3;           // staging row group 0..3
    int ldc = (lane & 7) * 4;      // staging col 0,4,...,28

    int C2  = 2 * tg;
    int Lw0 = gr * 4 + (C2 & 3);
    int Lw1 = gr * 4 + ((C2 + 1) & 3);
    int rr  = (C2 & 4) >> 1;
    int wo0 = (Lw0 ^ ((Lw0 >> 3) & 3)) * 4 + rr;
    int wo1 = (Lw1 ^ ((Lw1 >> 3) & 3)) * 4 + rr;

    for (int ch = 0; ch < 8; ch++) {
        int cbm = ch * 32;
        {
            float4 bm[8];
#pragma unroll
            for (int i = 0; i < 8; i++) {
                int n = i * 4 + ldr;
                float4 bv = *(const float4*)(Bb + ((size_t)n << 8) + cbm + ldc);
                float4 mv = *(const float4*)(Mb + ((size_t)n << 8) + cbm + ldc);
                bm[i] = make_float4(bv.x + mv.x, bv.y + mv.y,
                                    bv.z + mv.z, bv.w + mv.w);
            }
#pragma unroll
            for (int i = 0; i < 8; i++) {
                int n = i * 4 + ldr;
                *(float4*)(Pf + n * 32 + (ldc ^ ((n & 3) << 3))) = bm[i];
            }
        }
        __syncwarp();

        float4 S[2][4];
#pragma unroll
        for (int mi = 0; mi < 2; mi++)
#pragma unroll
            for (int nt = 0; nt < 4; nt++) S[mi][nt] = make_float4(0.f, 0.f, 0.f, 0.f);
#pragma unroll
        for (int kt = 0; kt < 4; kt++) {
#pragma unroll
            for (int nt = 0; nt < 4; nt++) {
                uint2 bk = *(const uint2*)&Ks[((kt * 32 + ch * 4 + nt) * 32 + lane) * 2];
                mma8(S[0][nt], qa[0][kt], bk);
                mma8(S[1][nt], qa[1][kt], bk);
            }
        }

#pragma unroll
        for (int mi = 0; mi < 2; mi++) {
            float2 bmf[4][2];
#pragma unroll
            for (int nt = 0; nt < 4; nt++) {
#pragma unroll
                for (int r2 = 0; r2 < 2; r2++) {
                    int n = mi * 16 + r2 * 8 + gr;
                    int m = nt * 8 + C2;
                    bmf[nt][r2] = *(const float2*)(Pf + n * 32 + (m ^ ((n & 3) << 3)));
                }
            }
            uint2 u0[4], u1[4];
            float ls0 = 0.f, ls1 = 0.f;
#pragma unroll
            for (int nt = 0; nt < 4; nt++) {
                float4 s = S[mi][nt];
                float p00 = __expf(s.x + bmf[nt][0].x);
                float p01 = __expf(s.y + bmf[nt][0].y);
                float p10 = __expf(s.z + bmf[nt][1].x);
                float p11 = __expf(s.w + bmf[nt][1].y);
                ls0 += p00 + p01;
                ls1 += p10 + p11;
                u0[nt].x = to_tf32(p00); u0[nt].y = to_tf32(p10);
                u1[nt].x = to_tf32(p01); u1[nt].y = to_tf32(p11);
            }
            lsum[mi][0] += ls0;
            lsum[mi][1] += ls1;
            __syncwarp();
#pragma unroll
            for (int nt = 0; nt < 4; nt++) {
                uint* tile = Ps + (mi * 4 + nt) * 128;
                *(uint2*)&tile[wo0] = u0[nt];
                *(uint2*)&tile[wo1] = u1[nt];
            }
        }
        __syncwarp();

#pragma unroll
        for (int kf = 0; kf < 4; kf++) {
            uint4 a0 = *(const uint4*)&Ps[(0 * 4 + kf) * 128 + fl];
            uint4 a1 = *(const uint4*)&Ps[(1 * 4 + kf) * 128 + fl];
#pragma unroll
            for (int nt = 0; nt < 4; nt++) {
                uint2 bv = *(const uint2*)&Vs[(((ch * 4 + kf) * 4 + nt) * 32 + lane) * 2];
                mma8(O[0][nt], a0, bv);
                mma8(O[1][nt], a1, bv);
            }
        }
        __syncwarp();
    }

    float inv[2][2];
#pragma unroll
    for (int mi = 0; mi < 2; mi++)
#pragma unroll
        for (int r2 = 0; r2 < 2; r2++) {
            float lv = lsum[mi][r2];
            lv += __shfl_xor_sync(0xffffffff, lv, 1);
            lv += __shfl_xor_sync(0xffffffff, lv, 2);
            inv[mi][r2] = 1.f / lv;
        }
#pragma unroll
    for (int mi = 0; mi < 2; mi++) {
#pragma unroll
        for (int nt = 0; nt < 4; nt++) {
            float4 o = O[mi][nt];
            int row0 = qb + mi * 16 + gr;
            int d = h * HD + nt * 8 + C2;
            *(float2*)&g_att[((size_t)(b * NTOK) + row0) * DIM + d] =
                make_float2(o.x * inv[mi][0], o.y * inv[mi][0]);
            *(float2*)&g_att[((size_t)(b * NTOK) + row0 + 8) * DIM + d] =
                make_float2(o.z * inv[mi][1], o.w * inv[mi][1]);
        }
    }
}

// ---------------------------------------------------------------------------
// Launch
// ---------------------------------------------------------------------------
extern "C" void kernel_launch(void* const* d_in, const int* in_sizes, int n_in,
                              void* d_out, int out_size) {
    const float* x        = (const float*)d_in[0];
    const float* mask     = (const float*)d_in[1];
    const float* qkv_w    = (const float*)d_in[2];
    const float* qkv_b    = (const float*)d_in[3];
    const float* proj_w   = (const float*)d_in[4];
    const float* proj_b   = (const float*)d_in[5];
    const float* table    = (const float*)d_in[6];
    const int*   rel      = (const int*)d_in[7];
    float* out = (float*)d_out;

    cudaFuncSetAttribute(attn_tc_kernel,
                         cudaFuncAttributeMaxDynamicSharedMemorySize, 98304);
    cudaFuncSetAttribute(qkv_gemm_kernel,
                         cudaFuncAttributeMaxDynamicSharedMemorySize, 81920);
    cudaFuncSetAttribute(proj_gemm_kernel,
                         cudaFuncAttributeMaxDynamicSharedMemorySize, 81920);

    bias_gather_kernel<<<HEADS * NTOK * NTOK / 256, 256>>>(table, rel);
    qkv_gemm_kernel<<<dim3(3, ROWS / 128), 512, 81920>>>(x, qkv_w, qkv_b);
    attn_tc_kernel<<<dim3(HEADS, BATCH), 256, 98304>>>(mask);
    proj_gemm_kernel<<<dim3(1, ROWS / 128), 512, 81920>>>(proj_w, proj_b, out);
}

// round 11
// speedup vs baseline: 1.2911x; 1.2911x over previous
#include <cuda_runtime.h>
#include <cuda_fp16.h>

// Problem constants
#define BATCH   256          // B_
#define NTOK    256          // N tokens per window
#define DIM     192
#define HEADS   6
#define HD      32           // head dim
#define NW      64           // number of windows (mask slices)
#define ROWS    (BATCH*NTOK) // 65536 GEMM rows
#define SCALE   0.17677669529663687f   // 32^-0.5

typedef unsigned int uint;

// ---------------------------------------------------------------------------
// fp16 mma helpers (m16n8k16; gr=lane>>2, tg=lane&3)
//   A(16x16): a0=rows gr, k 2tg:2tg+1 | a1=rows gr+8 same k | a2/a3 = k+8
//   B(16x8):  b0=k 2tg:2tg+1, col gr  | b1=k+8
//   C(16x8):  c0=(gr,2tg) c1=(gr,2tg+1) c2=(gr+8,2tg) c3=(gr+8,2tg+1)
// ---------------------------------------------------------------------------
__device__ __forceinline__ uint pkh2(float lo, float hi) {
    __half2 h = __floats2half2_rn(lo, hi);
    return *(uint*)&h;
}
__device__ __forceinline__ void mma16(float4& c, uint4 a, uint2 b) {
    asm("mma.sync.aligned.m16n8k16.row.col.f32.f16.f16.f32 "
        "{%0,%1,%2,%3},{%4,%5,%6,%7},{%8,%9},{%0,%1,%2,%3};"
        : "+f"(c.x), "+f"(c.y), "+f"(c.z), "+f"(c.w)
        : "r"(a.x), "r"(a.y), "r"(a.z), "r"(a.w), "r"(b.x), "r"(b.y));
}

// ---------------------------------------------------------------------------
// Scratch (device globals). q/k/v/att stored as packed f16 pairs (u32):
//   g_q/g_k/g_v: [b*6+h][tok][16 u32]  (u32 = halves d, d+1)
//   g_att:       [row][96 u32]         (u32 = halves c, c+1)
// ---------------------------------------------------------------------------
__device__ uint  g_q[BATCH*HEADS*NTOK*16];
__device__ uint  g_k[BATCH*HEADS*NTOK*16];
__device__ uint  g_v[BATCH*HEADS*NTOK*16];
__device__ uint  g_att[ROWS*96];
__device__ float g_bias[HEADS*NTOK*NTOK];   // gathered bias [h][n][m]

// ---------------------------------------------------------------------------
// Prep: bias gather [h][n][m]
// ---------------------------------------------------------------------------
__global__ void bias_gather_kernel(const float* __restrict__ table,
                                   const int* __restrict__ rel) {
    int idx = blockIdx.x * 256 + threadIdx.x;
    int m = idx & 255;
    int n = (idx >> 8) & 255;
    int h = idx >> 16;
    g_bias[idx] = table[rel[(n << 8) + m] * HEADS + h];
}

// ---------------------------------------------------------------------------
// fp16 GEMM core: CTA 128(M) x 192(N), K in 6 stages of 32. 256 thr, 8 warps
// 2(M)x4(N), warp tile 64x48. smem (static 20KB):
//   As[row(128)][k2(16)] u32, swizzle col ^ ((row&7)<<1)
//   Bs[n(192)][k2(16)]  u32 (B pre-transposed during staging), same swizzle
// ---------------------------------------------------------------------------
__device__ __forceinline__ uint4 ldA16(const uint* As, int mtb, int kc,
                                       int gr, int tg) {
    int r0 = mtb + gr;
    int s  = (r0 & 7) << 1;
    int c0 = (kc * 8 + tg) ^ s;
    int c1 = (kc * 8 + tg + 4) ^ s;
    uint4 a;
    a.x = As[r0 * 16 + c0];
    a.y = As[(r0 + 8) * 16 + c0];
    a.z = As[r0 * 16 + c1];
    a.w = As[(r0 + 8) * 16 + c1];
    return a;
}
__device__ __forceinline__ uint2 ldB16(const uint* Bs, int ntb, int kc,
                                       int gr, int tg) {
    int n0 = ntb + gr;
    int s  = (n0 & 7) << 1;
    uint2 b;
    b.x = Bs[n0 * 16 + ((kc * 8 + tg) ^ s)];
    b.y = Bs[n0 * 16 + ((kc * 8 + tg + 4) ^ s)];
    return b;
}
// stage B transposed: W[k][n] f32 -> Bs[n][k2] u32 (packed k-pairs)
__device__ __forceinline__ void stageB(uint* Bs, const float* __restrict__ W,
                                       int ldw, int kb, int cbW,
                                       int lane, int wid) {
#pragma unroll
    for (int j = 0; j < 12; j++) {
        int n  = (j % 6) * 32 + lane;
        int ki = wid + 8 * (j / 6);
        float w0 = W[(size_t)(kb + 2 * ki) * ldw + cbW + n];
        float w1 = W[(size_t)(kb + 2 * ki + 1) * ldw + cbW + n];
        Bs[n * 16 + (ki ^ ((n & 7) << 1))] = pkh2(w0, w1);
    }
}

#define GEMM_COMPUTE()                                                         \
    _Pragma("unroll")                                                          \
    for (int kc = 0; kc < 2; kc++) {                                           \
        uint4 a[4];                                                            \
        _Pragma("unroll")                                                      \
        for (int mt = 0; mt < 4; mt++)                                         \
            a[mt] = ldA16(As, wm * 64 + mt * 16, kc, gr, tg);                  \
        _Pragma("unroll")                                                      \
        for (int nt = 0; nt < 6; nt++) {                                       \
            uint2 b = ldB16(Bs, wn * 48 + nt * 8, kc, gr, tg);                 \
            _Pragma("unroll")                                                  \
            for (int mt = 0; mt < 4; mt++) mma16(acc[mt][nt], a[mt], b);       \
        }                                                                      \
    }

// QKV GEMM: grid (3, 512); block x = mat (0=Q,1=K,2=V)
__global__ __launch_bounds__(256) void qkv_gemm_kernel(
    const float* __restrict__ X, const float* __restrict__ W,
    const float* __restrict__ bias) {
    __shared__ uint As[128 * 16];
    __shared__ uint Bs[192 * 16];
    __shared__ float sBias[192];

    int t    = threadIdx.x;
    int lane = t & 31;
    int wid  = t >> 5;
    int wm   = wid >> 2;
    int wn   = wid & 3;
    int gr   = lane >> 2, tg = lane & 3;
    int mat  = blockIdx.x;
    int rb   = blockIdx.y * 128;
    int cb   = mat * 192;

    if (t < 192) sBias[t] = bias[cb + t];

    float4 acc[4][6];
#pragma unroll
    for (int i = 0; i < 4; i++)
#pragma unroll
        for (int j = 0; j < 6; j++) acc[i][j] = make_float4(0.f, 0.f, 0.f, 0.f);

    for (int i = 0; i < 6; i++) {
        int kb = i * 32;
        // stage A (f32 -> f16 pairs, swizzled)
#pragma unroll
        for (int ii = 0; ii < 4; ii++) {
            int fid = t + ii * 256;
            int row = fid >> 3;
            int c4  = (fid & 7) * 4;
            float4 v = *(const float4*)&X[(size_t)(rb + row) * DIM + kb + c4];
            uint2 u;
            u.x = pkh2(v.x, v.y);
            u.y = pkh2(v.z, v.w);
            int col = (c4 >> 1) ^ ((row & 7) << 1);
            *(uint2*)&As[row * 16 + col] = u;
        }
        stageB(Bs, W, 576, kb, cb, lane, wid);
        __syncthreads();
        GEMM_COMPUTE()
        __syncthreads();
    }

    uint* dst = (mat == 0) ? g_q : (mat == 1) ? g_k : g_v;
    float sc = (mat == 0) ? SCALE : 1.f;
#pragma unroll
    for (int mt = 0; mt < 4; mt++) {
#pragma unroll
        for (int nt = 0; nt < 6; nt++) {
            float4 c = acc[mt][nt];
            int cl = wn * 48 + nt * 8 + 2 * tg;
            float b0 = sBias[cl], b1 = sBias[cl + 1];
            int h = cl >> 5, d2 = (cl & 31) >> 1;
            int r0 = rb + wm * 64 + mt * 16 + gr;
            uint u0 = pkh2((c.x + b0) * sc, (c.y + b1) * sc);
            uint u1 = pkh2((c.z + b0) * sc, (c.w + b1) * sc);
            dst[(((r0 >> 8) * HEADS + h) * 256 + (r0 & 255)) * 16 + d2] = u0;
            int r1 = r0 + 8;
            dst[(((r1 >> 8) * HEADS + h) * 256 + (r1 & 255)) * 16 + d2] = u1;
        }
    }
}

// Proj GEMM: grid (1, 512). A from packed g_att (no cvt), output f32.
__global__ __launch_bounds__(256) void proj_gemm_kernel(
    const float* __restrict__ W, const float* __restrict__ bias,
    float* __restrict__ out) {
    __shared__ uint As[128 * 16];
    __shared__ uint Bs[192 * 16];
    __shared__ float sBias[192];

    int t    = threadIdx.x;
    int lane = t & 31;
    int wid  = t >> 5;
    int wm   = wid >> 2;
    int wn   = wid & 3;
    int gr   = lane >> 2, tg = lane & 3;
    int rb   = blockIdx.y * 128;

    if (t < 192) sBias[t] = bias[t];

    float4 acc[4][6];
#pragma unroll
    for (int i = 0; i < 4; i++)
#pragma unroll
        for (int j = 0; j < 6; j++) acc[i][j] = make_float4(0.f, 0.f, 0.f, 0.f);

    for (int i = 0; i < 6; i++) {
        int kb2 = i * 16;   // u32 k-col base
#pragma unroll
        for (int ii = 0; ii < 4; ii++) {
            int fid = t + ii * 256;
            int row = fid >> 3;
            int c2  = (fid & 7) * 2;
            uint2 v = *(const uint2*)&g_att[(size_t)(rb + row) * 96 + kb2 + c2];
            int col = c2 ^ ((row & 7) << 1);
            *(uint2*)&As[row * 16 + col] = v;
        }
        stageB(Bs, W, DIM, i * 32, 0, lane, wid);
        __syncthreads();
        GEMM_COMPUTE()
        __syncthreads();
    }

#pragma unroll
    for (int mt = 0; mt < 4; mt++) {
#pragma unroll
        for (int nt = 0; nt < 6; nt++) {
            float4 c = acc[mt][nt];
            int cl = wn * 48 + nt * 8 + 2 * tg;
            float b0 = sBias[cl], b1 = sBias[cl + 1];
            int r0 = rb + wm * 64 + mt * 16 + gr;
            *(float2*)&out[(size_t)r0 * DIM + cl] =
                make_float2(c.x + b0, c.y + b1);
            *(float2*)&out[(size_t)(r0 + 8) * DIM + cl] =
                make_float2(c.z + b0, c.w + b1);
        }
    }
}

// ---------------------------------------------------------------------------
// fp16 tensor-core attention. One CTA per (b,h); 8 warps x 32 query rows.
// smem 64KB: Ks[256][16]u32 (16K), Vs[128 key2][32 d]u32 (16K),
//            WB 8 x 4KB per-warp bias+mask bufs (32K; first reused as Qs).
// P never touches smem: fp16 C-frag pairs pack directly into A-frags.
// ---------------------------------------------------------------------------
__global__ __launch_bounds__(256, 2) void attn_f16_kernel(
    const float* __restrict__ mask) {
    extern __shared__ uint sm[];
    uint* Ks  = sm;                 // 4096 u32
    uint* Vs  = sm + 4096;          // 4096 u32
    uint* Qs  = sm + 8192;          // 4096 u32 (transient, inside WB)
    float* WB = (float*)(sm + 8192);// 8192 f32 (8 x 1024 per-warp)

    int h = blockIdx.x;
    int b = blockIdx.y;
    int w = b & (NW - 1);
    int t = threadIdx.x;
    int lane = t & 31;
    int wid = t >> 5;
    int gr = lane >> 2, tg = lane & 3;

    const uint* kg = g_k + (size_t)(b * HEADS + h) * (256 * 16);
    const uint* qg = g_q + (size_t)(b * HEADS + h) * (256 * 16);
    const uint* vg = g_v + (size_t)(b * HEADS + h) * (256 * 16);

    // stage K and Q: row copies with pair-swizzle
#pragma unroll
    for (int i = 0; i < 8; i++) {
        int fid = t + i * 256;          // 2048 uint2
        int key = fid >> 3;
        int p   = (fid & 7) * 2;
        int col = p ^ ((key & 7) << 1);
        *(uint2*)&Ks[key * 16 + col] = *(const uint2*)&kg[key * 16 + p];
        *(uint2*)&Qs[key * 16 + col] = *(const uint2*)&qg[key * 16 + p];
    }
    // stage V with key-pair interleave: Vs[key2][d] = (V[2k2][d], V[2k2+1][d])
#pragma unroll
    for (int i = 0; i < 4; i++) {
        int fid = t + i * 256;          // 1024 uint4
        int k2  = fid >> 3;
        int dg  = (fid & 7) * 4;        // d base, 4-aligned
        uint2 r0 = *(const uint2*)&vg[(2 * k2) * 16 + (dg >> 1)];
        uint2 r1 = *(const uint2*)&vg[(2 * k2 + 1) * 16 + (dg >> 1)];
        uint4 o;
        o.x = __byte_perm(r0.x, r1.x, 0x5410);
        o.y = __byte_perm(r0.x, r1.x, 0x7632);
        o.z = __byte_perm(r0.y, r1.y, 0x5410);
        o.w = __byte_perm(r0.y, r1.y, 0x7632);
        *(uint4*)&Vs[k2 * 32 + (dg ^ ((k2 & 3) << 3))] = o;
    }
    __syncthreads();

    int qb = wid * 32;
    uint4 qa[2][2];
#pragma unroll
    for (int mi = 0; mi < 2; mi++) {
#pragma unroll
        for (int kc = 0; kc < 2; kc++) {
            int r0 = qb + mi * 16 + gr;
            int s  = (r0 & 7) << 1;
            qa[mi][kc].x = Qs[r0 * 16 + ((kc * 8 + tg) ^ s)];
            qa[mi][kc].y = Qs[(r0 + 8) * 16 + ((kc * 8 + tg) ^ s)];
            qa[mi][kc].z = Qs[r0 * 16 + ((kc * 8 + tg + 4) ^ s)];
            qa[mi][kc].w = Qs[(r0 + 8) * 16 + ((kc * 8 + tg + 4) ^ s)];
        }
    }
    __syncthreads();   // Qs region now free -> per-warp WB

    float* Pf = WB + wid * 1024;
    float4 O[2][4];
#pragma unroll
    for (int mi = 0; mi < 2; mi++)
#pragma unroll
        for (int nt = 0; nt < 4; nt++) O[mi][nt] = make_float4(0.f, 0.f, 0.f, 0.f);
    float lsum[2][2] = {{0.f, 0.f}, {0.f, 0.f}};

    const float* Bb = g_bias + ((size_t)h << 16) + ((size_t)qb << 8);
    const float* Mb = mask   + ((size_t)w << 16) + ((size_t)qb << 8);
    int ldr = lane >> 3;
    int ldc = (lane & 7) * 4;
    int C2  = 2 * tg;

    for (int ch = 0; ch < 8; ch++) {
        int cbm = ch * 32;
        // ---- stage bias+mask 32x32 into per-warp buf (coalesced, swizzled) ----
        {
            float4 bm[8];
#pragma unroll
            for (int i = 0; i < 8; i++) {
                int n = i * 4 + ldr;
                float4 bv = *(const float4*)(Bb + ((size_t)n << 8) + cbm + ldc);
                float4 mv = *(const float4*)(Mb + ((size_t)n << 8) + cbm + ldc);
                bm[i] = make_float4(bv.x + mv.x, bv.y + mv.y,
                                    bv.z + mv.z, bv.w + mv.w);
            }
#pragma unroll
            for (int i = 0; i < 8; i++) {
                int n = i * 4 + ldr;
                *(float4*)(Pf + n * 32 + (ldc ^ ((n & 3) << 3))) = bm[i];
            }
        }
        __syncwarp();

        // ---- S = Q * K^T (32 keys) ----
        float4 S[2][4];
#pragma unroll
        for (int mi = 0; mi < 2; mi++)
#pragma unroll
            for (int nt = 0; nt < 4; nt++) S[mi][nt] = make_float4(0.f, 0.f, 0.f, 0.f);
#pragma unroll
        for (int kc = 0; kc < 2; kc++) {
#pragma unroll
            for (int nt = 0; nt < 4; nt++) {
                int key = ch * 32 + nt * 8 + gr;
                int s2  = (key & 7) << 1;
                uint2 bk;
                bk.x = Ks[key * 16 + ((kc * 8 + tg) ^ s2)];
                bk.y = Ks[key * 16 + ((kc * 8 + tg + 4) ^ s2)];
                mma16(S[0][nt], qa[0][kc], bk);
                mma16(S[1][nt], qa[1][kc], bk);
            }
        }

        // ---- softmax numerators; pack P straight into fp16 A-frags ----
        uint4 pa[2][2];
#pragma unroll
        for (int mi = 0; mi < 2; mi++) {
#pragma unroll
            for (int nt = 0; nt < 4; nt++) {
                int n0 = mi * 16 + gr;
                int m  = nt * 8 + C2;
                float2 bm0 = *(const float2*)(Pf + n0 * 32 + (m ^ ((n0 & 3) << 3)));
                int n1 = n0 + 8;
                float2 bm1 = *(const float2*)(Pf + n1 * 32 + (m ^ ((n1 & 3) << 3)));
                float4 s = S[mi][nt];
                float p00 = __expf(s.x + bm0.x);
                float p01 = __expf(s.y + bm0.y);
                float p10 = __expf(s.z + bm1.x);
                float p11 = __expf(s.w + bm1.y);
                lsum[mi][0] += p00 + p01;
                lsum[mi][1] += p10 + p11;
                uint lo = pkh2(p00, p01);
                uint hi = pkh2(p10, p11);
                int j = nt >> 1;
                if ((nt & 1) == 0) { pa[mi][j].x = lo; pa[mi][j].y = hi; }
                else               { pa[mi][j].z = lo; pa[mi][j].w = hi; }
            }
        }
        __syncwarp();   // bm reads done before next chunk overwrites

        // ---- O += P * V ----
#pragma unroll
        for (int j = 0; j < 2; j++) {
            int k2b = ch * 16 + j * 8;
            int rA = k2b + tg, rB = k2b + tg + 4;
#pragma unroll
            for (int nt = 0; nt < 4; nt++) {
                int d0 = nt * 8 + gr;
                uint2 vb;
                vb.x = Vs[rA * 32 + (d0 ^ ((rA & 3) << 3))];
                vb.y = Vs[rB * 32 + (d0 ^ ((rB & 3) << 3))];
                mma16(O[0][nt], pa[0][j], vb);
                mma16(O[1][nt], pa[1][j], vb);
            }
        }
    }

    // normalize + pack to g_att (u32 pairs)
    float inv[2][2];
#pragma unroll
    for (int mi = 0; mi < 2; mi++)
#pragma unroll
        for (int r2 = 0; r2 < 2; r2++) {
            float lv = lsum[mi][r2];
            lv += __shfl_xor_sync(0xffffffff, lv, 1);
            lv += __shfl_xor_sync(0xffffffff, lv, 2);
            inv[mi][r2] = 1.f / lv;
        }
#pragma unroll
    for (int mi = 0; mi < 2; mi++) {
#pragma unroll
        for (int nt = 0; nt < 4; nt++) {
            float4 o = O[mi][nt];
            int r0 = b * 256 + qb + mi * 16 + gr;
            int col = h * 16 + nt * 4 + tg;
            g_att[(size_t)r0 * 96 + col] =
                pkh2(o.x * inv[mi][0], o.y * inv[mi][0]);
            g_att[(size_t)(r0 + 8) * 96 + col] =
                pkh2(o.z * inv[mi][1], o.w * inv[mi][1]);
        }
    }
}

// ---------------------------------------------------------------------------
// Launch
// ---------------------------------------------------------------------------
extern "C" void kernel_launch(void* const* d_in, const int* in_sizes, int n_in,
                              void* d_out, int out_size) {
    const float* x        = (const float*)d_in[0];
    const float* mask     = (const float*)d_in[1];
    const float* qkv_w    = (const float*)d_in[2];
    const float* qkv_b    = (const float*)d_in[3];
    const float* proj_w   = (const float*)d_in[4];
    const float* proj_b   = (const float*)d_in[5];
    const float* table    = (const float*)d_in[6];
    const int*   rel      = (const int*)d_in[7];
    float* out = (float*)d_out;

    cudaFuncSetAttribute(attn_f16_kernel,
                         cudaFuncAttributeMaxDynamicSharedMemorySize, 65536);

    bias_gather_kernel<<<HEADS * NTOK * NTOK / 256, 256>>>(table, rel);
    qkv_gemm_kernel<<<dim3(3, ROWS / 128), 256>>>(x, qkv_w, qkv_b);
    attn_f16_kernel<<<dim3(HEADS, BATCH), 256, 65536>>>(mask);
    proj_gemm_kernel<<<dim3(1, ROWS / 128), 256>>>(proj_w, proj_b, out);
}

// round 12
// speedup vs baseline: 1.5761x; 1.2207x over previous
#include <cuda_runtime.h>
#include <cuda_fp16.h>

// Problem constants
#define BATCH   256          // B_
#define NTOK    256          // N tokens per window
#define DIM     192
#define HEADS   6
#define HD      32           // head dim
#define NW      64           // number of windows (mask slices)
#define ROWS    (BATCH*NTOK) // 65536 GEMM rows
#define SCALE   0.17677669529663687f   // 32^-0.5

typedef unsigned int uint;

// ---------------------------------------------------------------------------
// fp16 mma helpers (m16n8k16; gr=lane>>2, tg=lane&3)
// ---------------------------------------------------------------------------
__device__ __forceinline__ uint pkh2(float lo, float hi) {
    __half2 h = __floats2half2_rn(lo, hi);
    return *(uint*)&h;
}
__device__ __forceinline__ void mma16(float4& c, uint4 a, uint2 b) {
    asm("mma.sync.aligned.m16n8k16.row.col.f32.f16.f16.f32 "
        "{%0,%1,%2,%3},{%4,%5,%6,%7},{%8,%9},{%0,%1,%2,%3};"
        : "+f"(c.x), "+f"(c.y), "+f"(c.z), "+f"(c.w)
        : "r"(a.x), "r"(a.y), "r"(a.z), "r"(a.w), "r"(b.x), "r"(b.y));
}

// ---------------------------------------------------------------------------
// Scratch. q/k/v/att as packed f16 pairs:
//   g_q/g_k/g_v: [b*6+h][tok][16 u32], g_att: [row][96 u32]
// ---------------------------------------------------------------------------
__device__ uint  g_q[BATCH*HEADS*NTOK*16];
__device__ uint  g_k[BATCH*HEADS*NTOK*16];
__device__ uint  g_v[BATCH*HEADS*NTOK*16];
__device__ uint  g_att[ROWS*96];
__device__ float g_bias[HEADS*NTOK*NTOK];   // gathered bias [h][n][m]

__global__ void bias_gather_kernel(const float* __restrict__ table,
                                   const int* __restrict__ rel) {
    int idx = blockIdx.x * 256 + threadIdx.x;
    int m = idx & 255;
    int n = (idx >> 8) & 255;
    int h = idx >> 16;
    g_bias[idx] = table[rel[(n << 8) + m] * HEADS + h];
}

// ---------------------------------------------------------------------------
// Resident-operand fp16 GEMM. CTA tile 128(M) x 192(N) x full-K(192).
// smem (dynamic 143360B): As[128 rows][112 u32] (k2 cols 0..95 + pad),
//                          Bs[192 n][112 u32]   (B transposed, k2 cols).
// Stride 112 (mod 32 == 16) keeps the row-parity bank bit -> frag LDS.32
// bank map is a bijection of lane bits (conflict-free).
// Swizzle within each 16-col chunk: c ^ ((row&7)<<1).
// 8 warps 2(M)x4(N), warp tile 64x48; 288 HMMAs unbroken per warp per slab.
// ---------------------------------------------------------------------------
#define ASTR 112
#define AS_WORDS (128 * ASTR)   // 14336
#define BS_WORDS (192 * ASTR)   // 21504
#define GEMM_SMEM ((AS_WORDS + BS_WORDS) * 4)   // 143360 B

__device__ __forceinline__ uint4 ldA16(const uint* As, int mtb, int kb2,
                                       int kc, int gr, int tg) {
    int r0 = mtb + gr;
    int s  = (r0 & 7) << 1;
    int c0 = kb2 * 16 + ((kc * 8 + tg) ^ s);
    int c1 = kb2 * 16 + ((kc * 8 + tg + 4) ^ s);
    uint4 a;
    a.x = As[r0 * ASTR + c0];
    a.y = As[(r0 + 8) * ASTR + c0];
    a.z = As[r0 * ASTR + c1];
    a.w = As[(r0 + 8) * ASTR + c1];
    return a;
}
__device__ __forceinline__ uint2 ldB16(const uint* Bs, int ntb, int kb2,
                                       int kc, int gr, int tg) {
    int n0 = ntb + gr;
    int s  = (n0 & 7) << 1;
    uint2 b;
    b.x = Bs[n0 * ASTR + kb2 * 16 + ((kc * 8 + tg) ^ s)];
    b.y = Bs[n0 * ASTR + kb2 * 16 + ((kc * 8 + tg + 4) ^ s)];
    return b;
}
// stage full B slab transposed: W[k][n] f32 -> Bs[n][k2] u32 (18432 u32)
__device__ __forceinline__ void stageB_full(uint* Bs, const float* __restrict__ W,
                                            int ldw, int cbW, int lane, int wid) {
#pragma unroll
    for (int j = 0; j < 72; j++) {
        int n  = (j % 6) * 32 + lane;
        int ki = wid + 8 * (j / 6);         // k2 index 0..95
        float w0 = W[(size_t)(2 * ki) * ldw + cbW + n];
        float w1 = W[(size_t)(2 * ki + 1) * ldw + cbW + n];
        int col = (ki & ~15) + ((ki & 15) ^ ((n & 7) << 1));
        Bs[n * ASTR + col] = pkh2(w0, w1);
    }
}

#define GEMM_COMPUTE_FULL()                                                    \
    _Pragma("unroll")                                                          \
    for (int kb2 = 0; kb2 < 6; kb2++) {                                        \
        _Pragma("unroll")                                                      \
        for (int kc = 0; kc < 2; kc++) {                                       \
            uint4 a[4];                                                        \
            _Pragma("unroll")                                                  \
            for (int mt = 0; mt < 4; mt++)                                     \
                a[mt] = ldA16(As, wm * 64 + mt * 16, kb2, kc, gr, tg);         \
            _Pragma("unroll")                                                  \
            for (int nt = 0; nt < 6; nt++) {                                   \
                uint2 b = ldB16(Bs, wn * 48 + nt * 8, kb2, kc, gr, tg);        \
                _Pragma("unroll")                                              \
                for (int mt = 0; mt < 4; mt++) mma16(acc[mt][nt], a[mt], b);   \
            }                                                                  \
        }                                                                      \
    }

// QKV GEMM: grid 512, one CTA per 128-row block; loops mats Q,K,V internally.
__global__ __launch_bounds__(256) void qkv_gemm_kernel(
    const float* __restrict__ X, const float* __restrict__ W,
    const float* __restrict__ bias) {
    extern __shared__ uint smg[];
    uint* As = smg;
    uint* Bs = smg + AS_WORDS;
    __shared__ float sBias[576];

    int t    = threadIdx.x;
    int lane = t & 31;
    int wid  = t >> 5;
    int wm   = wid >> 2;
    int wn   = wid & 3;
    int gr   = lane >> 2, tg = lane & 3;
    int rb   = blockIdx.x * 128;

    for (int i = t; i < 576; i += 256) sBias[i] = bias[i];

    // stage A once: 128x192 f32 -> f16 pairs, swizzled (24 float4 / thread)
#pragma unroll
    for (int ii = 0; ii < 24; ii++) {
        int fid = t + ii * 256;          // 6144 float4
        int row = fid / 48;
        int c4  = (fid - row * 48) * 4;  // f32 col, %4==0
        float4 v = *(const float4*)&X[(size_t)(rb + row) * DIM + c4];
        int c2 = c4 >> 1;                // u32 col 0..94 even
        int col = (c2 & ~15) + ((c2 & 15) ^ ((row & 7) << 1));
        uint2 u;
        u.x = pkh2(v.x, v.y);
        u.y = pkh2(v.z, v.w);
        *(uint2*)&As[row * ASTR + col] = u;
    }

    for (int mat = 0; mat < 3; mat++) {
        __syncthreads();   // prev compute done before B overwrite (A stage ok 1st)
        stageB_full(Bs, W, 576, mat * 192, lane, wid);
        __syncthreads();

        float4 acc[4][6];
#pragma unroll
        for (int i = 0; i < 4; i++)
#pragma unroll
            for (int j = 0; j < 6; j++) acc[i][j] = make_float4(0.f, 0.f, 0.f, 0.f);

        GEMM_COMPUTE_FULL()

        uint* dst = (mat == 0) ? g_q : (mat == 1) ? g_k : g_v;
        float sc = (mat == 0) ? SCALE : 1.f;
        int cbias = mat * 192;
#pragma unroll
        for (int mt = 0; mt < 4; mt++) {
#pragma unroll
            for (int nt = 0; nt < 6; nt++) {
                float4 c = acc[mt][nt];
                int cl = wn * 48 + nt * 8 + 2 * tg;
                float b0 = sBias[cbias + cl], b1 = sBias[cbias + cl + 1];
                int h = cl >> 5, d2 = (cl & 31) >> 1;
                int r0 = rb + wm * 64 + mt * 16 + gr;
                uint u0 = pkh2((c.x + b0) * sc, (c.y + b1) * sc);
                uint u1 = pkh2((c.z + b0) * sc, (c.w + b1) * sc);
                dst[(((r0 >> 8) * HEADS + h) * 256 + (r0 & 255)) * 16 + d2] = u0;
                int r1 = r0 + 8;
                dst[(((r1 >> 8) * HEADS + h) * 256 + (r1 & 255)) * 16 + d2] = u1;
            }
        }
    }
}

// Proj GEMM: grid 512; A from packed g_att (no cvt), B once, output f32.
__global__ __launch_bounds__(256) void proj_gemm_kernel(
    const float* __restrict__ W, const float* __restrict__ bias,
    float* __restrict__ out) {
    extern __shared__ uint smg[];
    uint* As = smg;
    uint* Bs = smg + AS_WORDS;
    __shared__ float sBias[192];

    int t    = threadIdx.x;
    int lane = t & 31;
    int wid  = t >> 5;
    int wm   = wid >> 2;
    int wn   = wid & 3;
    int gr   = lane >> 2, tg = lane & 3;
    int rb   = blockIdx.x * 128;

    if (t < 192) sBias[t] = bias[t];

    // stage A once: 128x96 u32, swizzled (24 uint2 / thread)
#pragma unroll
    for (int ii = 0; ii < 24; ii++) {
        int fid = t + ii * 256;          // 6144 uint2
        int row = fid / 48;
        int c2  = (fid - row * 48) * 2;  // u32 col, even
        uint2 v = *(const uint2*)&g_att[(size_t)(rb + row) * 96 + c2];
        int col = (c2 & ~15) + ((c2 & 15) ^ ((row & 7) << 1));
        *(uint2*)&As[row * ASTR + col] = v;
    }
    stageB_full(Bs, W, DIM, 0, lane, wid);
    __syncthreads();

    float4 acc[4][6];
#pragma unroll
    for (int i = 0; i < 4; i++)
#pragma unroll
        for (int j = 0; j < 6; j++) acc[i][j] = make_float4(0.f, 0.f, 0.f, 0.f);

    GEMM_COMPUTE_FULL()

#pragma unroll
    for (int mt = 0; mt < 4; mt++) {
#pragma unroll
        for (int nt = 0; nt < 6; nt++) {
            float4 c = acc[mt][nt];
            int cl = wn * 48 + nt * 8 + 2 * tg;
            float b0 = sBias[cl], b1 = sBias[cl + 1];
            int r0 = rb + wm * 64 + mt * 16 + gr;
            *(float2*)&out[(size_t)r0 * DIM + cl] =
                make_float2(c.x + b0, c.y + b1);
            *(float2*)&out[(size_t)(r0 + 8) * DIM + cl] =
                make_float2(c.z + b0, c.w + b1);
        }
    }
}

// ---------------------------------------------------------------------------
// fp16 tensor-core attention (unchanged, round-11). One CTA per (b,h).
// ---------------------------------------------------------------------------
__global__ __launch_bounds__(256, 2) void attn_f16_kernel(
    const float* __restrict__ mask) {
    extern __shared__ uint sm[];
    uint* Ks  = sm;                 // 4096 u32
    uint* Vs  = sm + 4096;          // 4096 u32
    uint* Qs  = sm + 8192;          // 4096 u32 (transient, inside WB)
    float* WB = (float*)(sm + 8192);// 8192 f32 (8 x 1024 per-warp)

    int h = blockIdx.x;
    int b = blockIdx.y;
    int w = b & (NW - 1);
    int t = threadIdx.x;
    int lane = t & 31;
    int wid = t >> 5;
    int gr = lane >> 2, tg = lane & 3;

    const uint* kg = g_k + (size_t)(b * HEADS + h) * (256 * 16);
    const uint* qg = g_q + (size_t)(b * HEADS + h) * (256 * 16);
    const uint* vg = g_v + (size_t)(b * HEADS + h) * (256 * 16);

#pragma unroll
    for (int i = 0; i < 8; i++) {
        int fid = t + i * 256;
        int key = fid >> 3;
        int p   = (fid & 7) * 2;
        int col = p ^ ((key & 7) << 1);
        *(uint2*)&Ks[key * 16 + col] = *(const uint2*)&kg[key * 16 + p];
        *(uint2*)&Qs[key * 16 + col] = *(const uint2*)&qg[key * 16 + p];
    }
#pragma unroll
    for (int i = 0; i < 4; i++) {
        int fid = t + i * 256;
        int k2  = fid >> 3;
        int dg  = (fid & 7) * 4;
        uint2 r0 = *(const uint2*)&vg[(2 * k2) * 16 + (dg >> 1)];
        uint2 r1 = *(const uint2*)&vg[(2 * k2 + 1) * 16 + (dg >> 1)];
        uint4 o;
        o.x = __byte_perm(r0.x, r1.x, 0x5410);
        o.y = __byte_perm(r0.x, r1.x, 0x7632);
        o.z = __byte_perm(r0.y, r1.y, 0x5410);
        o.w = __byte_perm(r0.y, r1.y, 0x7632);
        *(uint4*)&Vs[k2 * 32 + (dg ^ ((k2 & 3) << 3))] = o;
    }
    __syncthreads();

    int qb = wid * 32;
    uint4 qa[2][2];
#pragma unroll
    for (int mi = 0; mi < 2; mi++) {
#pragma unroll
        for (int kc = 0; kc < 2; kc++) {
            int r0 = qb + mi * 16 + gr;
            int s  = (r0 & 7) << 1;
            qa[mi][kc].x = Qs[r0 * 16 + ((kc * 8 + tg) ^ s)];
            qa[mi][kc].y = Qs[(r0 + 8) * 16 + ((kc * 8 + tg) ^ s)];
            qa[mi][kc].z = Qs[r0 * 16 + ((kc * 8 + tg + 4) ^ s)];
            qa[mi][kc].w = Qs[(r0 + 8) * 16 + ((kc * 8 + tg + 4) ^ s)];
        }
    }
    __syncthreads();   // Qs region now free -> per-warp WB

    float* Pf = WB + wid * 1024;
    float4 O[2][4];
#pragma unroll
    for (int mi = 0; mi < 2; mi++)
#pragma unroll
        for (int nt = 0; nt < 4; nt++) O[mi][nt] = make_float4(0.f, 0.f, 0.f, 0.f);
    float lsum[2][2] = {{0.f, 0.f}, {0.f, 0.f}};

    const float* Bb = g_bias + ((size_t)h << 16) + ((size_t)qb << 8);
    const float* Mb = mask   + ((size_t)w << 16) + ((size_t)qb << 8);
    int ldr = lane >> 3;
    int ldc = (lane & 7) * 4;
    int C2  = 2 * tg;

    for (int ch = 0; ch < 8; ch++) {
        int cbm = ch * 32;
        {
            float4 bm[8];
#pragma unroll
            for (int i = 0; i < 8; i++) {
                int n = i * 4 + ldr;
                float4 bv = *(const float4*)(Bb + ((size_t)n << 8) + cbm + ldc);
                float4 mv = *(const float4*)(Mb + ((size_t)n << 8) + cbm + ldc);
                bm[i] = make_float4(bv.x + mv.x, bv.y + mv.y,
                                    bv.z + mv.z, bv.w + mv.w);
            }
#pragma unroll
            for (int i = 0; i < 8; i++) {
                int n = i * 4 + ldr;
                *(float4*)(Pf + n * 32 + (ldc ^ ((n & 3) << 3))) = bm[i];
            }
        }
        __syncwarp();

        float4 S[2][4];
#pragma unroll
        for (int mi = 0; mi < 2; mi++)
#pragma unroll
            for (int nt = 0; nt < 4; nt++) S[mi][nt] = make_float4(0.f, 0.f, 0.f, 0.f);
#pragma unroll
        for (int kc = 0; kc < 2; kc++) {
#pragma unroll
            for (int nt = 0; nt < 4; nt++) {
                int key = ch * 32 + nt * 8 + gr;
                int s2  = (key & 7) << 1;
                uint2 bk;
                bk.x = Ks[key * 16 + ((kc * 8 + tg) ^ s2)];
                bk.y = Ks[key * 16 + ((kc * 8 + tg + 4) ^ s2)];
                mma16(S[0][nt], qa[0][kc], bk);
                mma16(S[1][nt], qa[1][kc], bk);
            }
        }

        uint4 pa[2][2];
#pragma unroll
        for (int mi = 0; mi < 2; mi++) {
#pragma unroll
            for (int nt = 0; nt < 4; nt++) {
                int n0 = mi * 16 + gr;
                int m  = nt * 8 + C2;
                float2 bm0 = *(const float2*)(Pf + n0 * 32 + (m ^ ((n0 & 3) << 3)));
                int n1 = n0 + 8;
                float2 bm1 = *(const float2*)(Pf + n1 * 32 + (m ^ ((n1 & 3) << 3)));
                float4 s = S[mi][nt];
                float p00 = __expf(s.x + bm0.x);
                float p01 = __expf(s.y + bm0.y);
                float p10 = __expf(s.z + bm1.x);
                float p11 = __expf(s.w + bm1.y);
                lsum[mi][0] += p00 + p01;
                lsum[mi][1] += p10 + p11;
                uint lo = pkh2(p00, p01);
                uint hi = pkh2(p10, p11);
                int j = nt >> 1;
                if ((nt & 1) == 0) { pa[mi][j].x = lo; pa[mi][j].y = hi; }
                else               { pa[mi][j].z = lo; pa[mi][j].w = hi; }
            }
        }
        __syncwarp();

#pragma unroll
        for (int j = 0; j < 2; j++) {
            int k2b = ch * 16 + j * 8;
            int rA = k2b + tg, rB = k2b + tg + 4;
#pragma unroll
            for (int nt = 0; nt < 4; nt++) {
                int d0 = nt * 8 + gr;
                uint2 vb;
                vb.x = Vs[rA * 32 + (d0 ^ ((rA & 3) << 3))];
                vb.y = Vs[rB * 32 + (d0 ^ ((rB & 3) << 3))];
                mma16(O[0][nt], pa[0][j], vb);
                mma16(O[1][nt], pa[1][j], vb);
            }
        }
    }

    float inv[2][2];
#pragma unroll
    for (int mi = 0; mi < 2; mi++)
#pragma unroll
        for (int r2 = 0; r2 < 2; r2++) {
            float lv = lsum[mi][r2];
            lv += __shfl_xor_sync(0xffffffff, lv, 1);
            lv += __shfl_xor_sync(0xffffffff, lv, 2);
            inv[mi][r2] = 1.f / lv;
        }
#pragma unroll
    for (int mi = 0; mi < 2; mi++) {
#pragma unroll
        for (int nt = 0; nt < 4; nt++) {
            float4 o = O[mi][nt];
            int r0 = b * 256 + qb + mi * 16 + gr;
            int col = h * 16 + nt * 4 + tg;
            g_att[(size_t)r0 * 96 + col] =
                pkh2(o.x * inv[mi][0], o.y * inv[mi][0]);
            g_att[(size_t)(r0 + 8) * 96 + col] =
                pkh2(o.z * inv[mi][1], o.w * inv[mi][1]);
        }
    }
}

// ---------------------------------------------------------------------------
// Launch
// ---------------------------------------------------------------------------
extern "C" void kernel_launch(void* const* d_in, const int* in_sizes, int n_in,
                              void* d_out, int out_size) {
    const float* x        = (const float*)d_in[0];
    const float* mask     = (const float*)d_in[1];
    const float* qkv_w    = (const float*)d_in[2];
    const float* qkv_b    = (const float*)d_in[3];
    const float* proj_w   = (const float*)d_in[4];
    const float* proj_b   = (const float*)d_in[5];
    const float* table    = (const float*)d_in[6];
    const int*   rel      = (const int*)d_in[7];
    float* out = (float*)d_out;

    cudaFuncSetAttribute(attn_f16_kernel,
                         cudaFuncAttributeMaxDynamicSharedMemorySize, 65536);
    cudaFuncSetAttribute(qkv_gemm_kernel,
                         cudaFuncAttributeMaxDynamicSharedMemorySize, GEMM_SMEM);
    cudaFuncSetAttribute(proj_gemm_kernel,
                         cudaFuncAttributeMaxDynamicSharedMemorySize, GEMM_SMEM);

    bias_gather_kernel<<<HEADS * NTOK * NTOK / 256, 256>>>(table, rel);
    qkv_gemm_kernel<<<ROWS / 128, 256, GEMM_SMEM>>>(x, qkv_w, qkv_b);
    attn_f16_kernel<<<dim3(HEADS, BATCH), 256, 65536>>>(mask);
    proj_gemm_kernel<<<ROWS / 128, 256, GEMM_SMEM>>>(proj_w, proj_b, out);
}

// round 13
// speedup vs baseline: 1.7245x; 1.0942x over previous
#include <cuda_runtime.h>
#include <cuda_fp16.h>

// Problem constants
#define BATCH   256          // B_
#define NTOK    256          // N tokens per window
#define DIM     192
#define HEADS   6
#define HD      32           // head dim
#define NW      64           // number of windows (mask slices)
#define ROWS    (BATCH*NTOK) // 65536 GEMM rows
#define SCALE   0.17677669529663687f   // 32^-0.5

typedef unsigned int uint;

// ---------------------------------------------------------------------------
// fp16 mma helpers (m16n8k16; gr=lane>>2, tg=lane&3)
// ---------------------------------------------------------------------------
__device__ __forceinline__ uint pkh2(float lo, float hi) {
    __half2 h = __floats2half2_rn(lo, hi);
    return *(uint*)&h;
}
__device__ __forceinline__ void mma16(float4& c, uint4 a, uint2 b) {
    asm("mma.sync.aligned.m16n8k16.row.col.f32.f16.f16.f32 "
        "{%0,%1,%2,%3},{%4,%5,%6,%7},{%8,%9},{%0,%1,%2,%3};"
        : "+f"(c.x), "+f"(c.y), "+f"(c.z), "+f"(c.w)
        : "r"(a.x), "r"(a.y), "r"(a.z), "r"(a.w), "r"(b.x), "r"(b.y));
}

// ---------------------------------------------------------------------------
// Scratch. q/k/v/att as packed f16 pairs:
//   g_q/g_k/g_v: [b*6+h][tok][16 u32], g_att: [row][96 u32]
// ---------------------------------------------------------------------------
__device__ uint  g_q[BATCH*HEADS*NTOK*16];
__device__ uint  g_k[BATCH*HEADS*NTOK*16];
__device__ uint  g_v[BATCH*HEADS*NTOK*16];
__device__ uint  g_att[ROWS*96];
__device__ float g_bias[HEADS*NTOK*NTOK];   // gathered bias [h][n][m]

__global__ void bias_gather_kernel(const float* __restrict__ table,
                                   const int* __restrict__ rel) {
    int idx = blockIdx.x * 256 + threadIdx.x;
    int m = idx & 255;
    int n = (idx >> 8) & 255;
    int h = idx >> 16;
    g_bias[idx] = table[rel[(n << 8) + m] * HEADS + h];
}

// ---------------------------------------------------------------------------
// fp16 GEMM, CTA tile 128(M) x 96(N) x full-K(192); grid (2, 512); 2 CTAs/SM.
// Chunk-major smem (stride 16 u32 -> bank = 16*row+col mod 32, conflict-free,
// validated round 11):
//   As[kb2(6)][row(128)][16 u32]   48KB   swizzle c ^ ((row&7)<<1)
//   Bs[kb2(6)][n(96)][16 u32]      36KB   (B transposed during staging)
// 8 warps 4(M)x2(N), warp tile 32x48; 144 HMMAs unbroken per warp per slab.
// ---------------------------------------------------------------------------
#define AS_WORDS (6 * 128 * 16)   // 12288
#define BS_WORDS (6 * 96 * 16)    //  9216
#define GEMM_SMEM ((AS_WORDS + BS_WORDS) * 4)   // 86016 B

__device__ __forceinline__ uint4 ldA16(const uint* As, int mtb, int kb2,
                                       int kc, int gr, int tg) {
    int r0 = mtb + gr;
    int s  = (r0 & 7) << 1;
    const uint* base = As + (kb2 * 128 + r0) * 16;
    int c0 = (kc * 8 + tg) ^ s;
    int c1 = (kc * 8 + tg + 4) ^ s;
    uint4 a;
    a.x = base[c0];
    a.y = base[128 + c0];   // row + 8
    a.z = base[c1];
    a.w = base[128 + c1];
    return a;
}
__device__ __forceinline__ uint2 ldB16(const uint* Bs, int ntb, int kb2,
                                       int kc, int gr, int tg) {
    int n0 = ntb + gr;
    int s  = (n0 & 7) << 1;
    const uint* base = Bs + (kb2 * 96 + n0) * 16;
    uint2 b;
    b.x = base[(kc * 8 + tg) ^ s];
    b.y = base[(kc * 8 + tg + 4) ^ s];
    return b;
}
// stage 96-col B slab transposed: W[k][cbW+n] f32 -> Bs[kb2][n][kil] u32
__device__ __forceinline__ void stageB96(uint* Bs, const float* __restrict__ W,
                                         int ldw, int cbW, int lane, int wid) {
#pragma unroll
    for (int j = 0; j < 36; j++) {
        int n  = (j % 3) * 32 + lane;        // 0..95
        int kg = wid + 8 * (j / 3);          // k2 index 0..95
        float w0 = W[(size_t)(2 * kg) * ldw + cbW + n];
        float w1 = W[(size_t)(2 * kg + 1) * ldw + cbW + n];
        int kb2 = kg >> 4;
        int col = (kg & 15) ^ ((n & 7) << 1);
        Bs[(kb2 * 96 + n) * 16 + col] = pkh2(w0, w1);
    }
}

#define GEMM_COMPUTE96()                                                       \
    _Pragma("unroll")                                                          \
    for (int kb2 = 0; kb2 < 6; kb2++) {                                        \
        _Pragma("unroll")                                                      \
        for (int kc = 0; kc < 2; kc++) {                                       \
            uint4 a[2];                                                        \
            a[0] = ldA16(As, wm * 32, kb2, kc, gr, tg);                        \
            a[1] = ldA16(As, wm * 32 + 16, kb2, kc, gr, tg);                   \
            _Pragma("unroll")                                                  \
            for (int nt = 0; nt < 6; nt++) {                                   \
                uint2 b = ldB16(Bs, wn * 48 + nt * 8, kb2, kc, gr, tg);        \
                mma16(acc[0][nt], a[0], b);                                    \
                mma16(acc[1][nt], a[1], b);                                    \
            }                                                                  \
        }                                                                      \
    }

// QKV GEMM: grid (2, 512); x = N-half, y = row block; loops mats Q,K,V.
__global__ __launch_bounds__(256, 2) void qkv_gemm_kernel(
    const float* __restrict__ X, const float* __restrict__ W,
    const float* __restrict__ bias) {
    extern __shared__ uint smg[];
    uint* As = smg;
    uint* Bs = smg + AS_WORDS;
    __shared__ float sBias[576];

    int t    = threadIdx.x;
    int lane = t & 31;
    int wid  = t >> 5;
    int wm   = wid >> 1;        // 0..3
    int wn   = wid & 1;         // 0..1
    int gr   = lane >> 2, tg = lane & 3;
    int nb   = blockIdx.x;      // N half
    int rb   = blockIdx.y * 128;

    for (int i = t; i < 576; i += 256) sBias[i] = bias[i];

    // stage A once: 128x192 f32 -> f16 pairs, chunk-major swizzled
#pragma unroll
    for (int ii = 0; ii < 24; ii++) {
        int fid = t + ii * 256;          // 6144 float4
        int row = fid / 48;
        int c4  = (fid - row * 48) * 4;  // f32 col
        float4 v = *(const float4*)&X[(size_t)(rb + row) * DIM + c4];
        int c2  = c4 >> 1;               // u32 col 0..94 even
        int kb2 = c2 >> 4;
        int col = (c2 & 15) ^ ((row & 7) << 1);
        uint2 u;
        u.x = pkh2(v.x, v.y);
        u.y = pkh2(v.z, v.w);
        *(uint2*)&As[(kb2 * 128 + row) * 16 + col] = u;
    }

    for (int mat = 0; mat < 3; mat++) {
        __syncthreads();   // prev compute done before B overwrite; A visible
        stageB96(Bs, W, 576, mat * 192 + nb * 96, lane, wid);
        __syncthreads();

        float4 acc[2][6];
#pragma unroll
        for (int i = 0; i < 2; i++)
#pragma unroll
            for (int j = 0; j < 6; j++) acc[i][j] = make_float4(0.f, 0.f, 0.f, 0.f);

        GEMM_COMPUTE96()

        uint* dst = (mat == 0) ? g_q : (mat == 1) ? g_k : g_v;
        float sc = (mat == 0) ? SCALE : 1.f;
#pragma unroll
        for (int mt = 0; mt < 2; mt++) {
#pragma unroll
            for (int nt = 0; nt < 6; nt++) {
                float4 c = acc[mt][nt];
                int cl = nb * 96 + wn * 48 + nt * 8 + 2 * tg;   // 0..190
                float b0 = sBias[mat * 192 + cl], b1 = sBias[mat * 192 + cl + 1];
                int h = cl >> 5, d2 = (cl & 31) >> 1;
                int r0 = rb + wm * 32 + mt * 16 + gr;
                uint u0 = pkh2((c.x + b0) * sc, (c.y + b1) * sc);
                uint u1 = pkh2((c.z + b0) * sc, (c.w + b1) * sc);
                dst[(((r0 >> 8) * HEADS + h) * 256 + (r0 & 255)) * 16 + d2] = u0;
                int r1 = r0 + 8;
                dst[(((r1 >> 8) * HEADS + h) * 256 + (r1 & 255)) * 16 + d2] = u1;
            }
        }
    }
}

// Proj GEMM: grid (2, 512); A from packed g_att, output f32.
__global__ __launch_bounds__(256, 2) void proj_gemm_kernel(
    const float* __restrict__ W, const float* __restrict__ bias,
    float* __restrict__ out) {
    extern __shared__ uint smg[];
    uint* As = smg;
    uint* Bs = smg + AS_WORDS;
    __shared__ float sBias[192];

    int t    = threadIdx.x;
    int lane = t & 31;
    int wid  = t >> 5;
    int wm   = wid >> 1;
    int wn   = wid & 1;
    int gr   = lane >> 2, tg = lane & 3;
    int nb   = blockIdx.x;
    int rb   = blockIdx.y * 128;

    if (t < 192) sBias[t] = bias[t];

    // stage A once: 128x96 u32 (already f16 pairs), chunk-major swizzled
#pragma unroll
    for (int ii = 0; ii < 24; ii++) {
        int fid = t + ii * 256;          // 6144 uint2
        int row = fid / 48;
        int c2  = (fid - row * 48) * 2;  // u32 col, even
        uint2 v = *(const uint2*)&g_att[(size_t)(rb + row) * 96 + c2];
        int kb2 = c2 >> 4;
        int col = (c2 & 15) ^ ((row & 7) << 1);
        *(uint2*)&As[(kb2 * 128 + row) * 16 + col] = v;
    }
    stageB96(Bs, W, DIM, nb * 96, lane, wid);
    __syncthreads();

    float4 acc[2][6];
#pragma unroll
    for (int i = 0; i < 2; i++)
#pragma unroll
        for (int j = 0; j < 6; j++) acc[i][j] = make_float4(0.f, 0.f, 0.f, 0.f);

    GEMM_COMPUTE96()

#pragma unroll
    for (int mt = 0; mt < 2; mt++) {
#pragma unroll
        for (int nt = 0; nt < 6; nt++) {
            float4 c = acc[mt][nt];
            int cl = nb * 96 + wn * 48 + nt * 8 + 2 * tg;
            float b0 = sBias[cl], b1 = sBias[cl + 1];
            int r0 = rb + wm * 32 + mt * 16 + gr;
            *(float2*)&out[(size_t)r0 * DIM + cl] =
                make_float2(c.x + b0, c.y + b1);
            *(float2*)&out[(size_t)(r0 + 8) * DIM + cl] =
                make_float2(c.z + b0, c.w + b1);
        }
    }
}

// ---------------------------------------------------------------------------
// fp16 tensor-core attention (unchanged, round-11 best). One CTA per (b,h).
// ---------------------------------------------------------------------------
__global__ __launch_bounds__(256, 2) void attn_f16_kernel(
    const float* __restrict__ mask) {
    extern __shared__ uint sm[];
    uint* Ks  = sm;                 // 4096 u32
    uint* Vs  = sm + 4096;          // 4096 u32
    uint* Qs  = sm + 8192;          // 4096 u32 (transient, inside WB)
    float* WB = (float*)(sm + 8192);// 8192 f32 (8 x 1024 per-warp)

    int h = blockIdx.x;
    int b = blockIdx.y;
    int w = b & (NW - 1);
    int t = threadIdx.x;
    int lane = t & 31;
    int wid = t >> 5;
    int gr = lane >> 2, tg = lane & 3;

    const uint* kg = g_k + (size_t)(b * HEADS + h) * (256 * 16);
    const uint* qg = g_q + (size_t)(b * HEADS + h) * (256 * 16);
    const uint* vg = g_v + (size_t)(b * HEADS + h) * (256 * 16);

#pragma unroll
    for (int i = 0; i < 8; i++) {
        int fid = t + i * 256;
        int key = fid >> 3;
        int p   = (fid & 7) * 2;
        int col = p ^ ((key & 7) << 1);
        *(uint2*)&Ks[key * 16 + col] = *(const uint2*)&kg[key * 16 + p];
        *(uint2*)&Qs[key * 16 + col] = *(const uint2*)&qg[key * 16 + p];
    }
#pragma unroll
    for (int i = 0; i < 4; i++) {
        int fid = t + i * 256;
        int k2  = fid >> 3;
        int dg  = (fid & 7) * 4;
        uint2 r0 = *(const uint2*)&vg[(2 * k2) * 16 + (dg >> 1)];
        uint2 r1 = *(const uint2*)&vg[(2 * k2 + 1) * 16 + (dg >> 1)];
        uint4 o;
        o.x = __byte_perm(r0.x, r1.x, 0x5410);
        o.y = __byte_perm(r0.x, r1.x, 0x7632);
        o.z = __byte_perm(r0.y, r1.y, 0x5410);
        o.w = __byte_perm(r0.y, r1.y, 0x7632);
        *(uint4*)&Vs[k2 * 32 + (dg ^ ((k2 & 3) << 3))] = o;
    }
    __syncthreads();

    int qb = wid * 32;
    uint4 qa[2][2];
#pragma unroll
    for (int mi = 0; mi < 2; mi++) {
#pragma unroll
        for (int kc = 0; kc < 2; kc++) {
            int r0 = qb + mi * 16 + gr;
            int s  = (r0 & 7) << 1;
            qa[mi][kc].x = Qs[r0 * 16 + ((kc * 8 + tg) ^ s)];
            qa[mi][kc].y = Qs[(r0 + 8) * 16 + ((kc * 8 + tg) ^ s)];
            qa[mi][kc].z = Qs[r0 * 16 + ((kc * 8 + tg + 4) ^ s)];
            qa[mi][kc].w = Qs[(r0 + 8) * 16 + ((kc * 8 + tg + 4) ^ s)];
        }
    }
    __syncthreads();   // Qs region now free -> per-warp WB

    float* Pf = WB + wid * 1024;
    float4 O[2][4];
#pragma unroll
    for (int mi = 0; mi < 2; mi++)
#pragma unroll
        for (int nt = 0; nt < 4; nt++) O[mi][nt] = make_float4(0.f, 0.f, 0.f, 0.f);
    float lsum[2][2] = {{0.f, 0.f}, {0.f, 0.f}};

    const float* Bb = g_bias + ((size_t)h << 16) + ((size_t)qb << 8);
    const float* Mb = mask   + ((size_t)w << 16) + ((size_t)qb << 8);
    int ldr = lane >> 3;
    int ldc = (lane & 7) * 4;
    int C2  = 2 * tg;

    for (int ch = 0; ch < 8; ch++) {
        int cbm = ch * 32;
        {
            float4 bm[8];
#pragma unroll
            for (int i = 0; i < 8; i++) {
                int n = i * 4 + ldr;
                float4 bv = *(const float4*)(Bb + ((size_t)n << 8) + cbm + ldc);
                float4 mv = *(const float4*)(Mb + ((size_t)n << 8) + cbm + ldc);
                bm[i] = make_float4(bv.x + mv.x, bv.y + mv.y,
                                    bv.z + mv.z, bv.w + mv.w);
            }
#pragma unroll
            for (int i = 0; i < 8; i++) {
                int n = i * 4 + ldr;
                *(float4*)(Pf + n * 32 + (ldc ^ ((n & 3) << 3))) = bm[i];
            }
        }
        __syncwarp();

        float4 S[2][4];
#pragma unroll
        for (int mi = 0; mi < 2; mi++)
#pragma unroll
            for (int nt = 0; nt < 4; nt++) S[mi][nt] = make_float4(0.f, 0.f, 0.f, 0.f);
#pragma unroll
        for (int kc = 0; kc < 2; kc++) {
#pragma unroll
            for (int nt = 0; nt < 4; nt++) {
                int key = ch * 32 + nt * 8 + gr;
                int s2  = (key & 7) << 1;
                uint2 bk;
                bk.x = Ks[key * 16 + ((kc * 8 + tg) ^ s2)];
                bk.y = Ks[key * 16 + ((kc * 8 + tg + 4) ^ s2)];
                mma16(S[0][nt], qa[0][kc], bk);
                mma16(S[1][nt], qa[1][kc], bk);
            }
        }

        uint4 pa[2][2];
#pragma unroll
        for (int mi = 0; mi < 2; mi++) {
#pragma unroll
            for (int nt = 0; nt < 4; nt++) {
                int n0 = mi * 16 + gr;
                int m  = nt * 8 + C2;
                float2 bm0 = *(const float2*)(Pf + n0 * 32 + (m ^ ((n0 & 3) << 3)));
                int n1 = n0 + 8;
                float2 bm1 = *(const float2*)(Pf + n1 * 32 + (m ^ ((n1 & 3) << 3)));
                float4 s = S[mi][nt];
                float p00 = __expf(s.x + bm0.x);
                float p01 = __expf(s.y + bm0.y);
                float p10 = __expf(s.z + bm1.x);
                float p11 = __expf(s.w + bm1.y);
                lsum[mi][0] += p00 + p01;
                lsum[mi][1] += p10 + p11;
                uint lo = pkh2(p00, p01);
                uint hi = pkh2(p10, p11);
                int j = nt >> 1;
                if ((nt & 1) == 0) { pa[mi][j].x = lo; pa[mi][j].y = hi; }
                else               { pa[mi][j].z = lo; pa[mi][j].w = hi; }
            }
        }
        __syncwarp();

#pragma unroll
        for (int j = 0; j < 2; j++) {
            int k2b = ch * 16 + j * 8;
            int rA = k2b + tg, rB = k2b + tg + 4;
#pragma unroll
            for (int nt = 0; nt < 4; nt++) {
                int d0 = nt * 8 + gr;
                uint2 vb;
                vb.x = Vs[rA * 32 + (d0 ^ ((rA & 3) << 3))];
                vb.y = Vs[rB * 32 + (d0 ^ ((rB & 3) << 3))];
                mma16(O[0][nt], pa[0][j], vb);
                mma16(O[1][nt], pa[1][j], vb);
            }
        }
    }

    float inv[2][2];
#pragma unroll
    for (int mi = 0; mi < 2; mi++)
#pragma unroll
        for (int r2 = 0; r2 < 2; r2++) {
            float lv = lsum[mi][r2];
            lv += __shfl_xor_sync(0xffffffff, lv, 1);
            lv += __shfl_xor_sync(0xffffffff, lv, 2);
            inv[mi][r2] = 1.f / lv;
        }
#pragma unroll
    for (int mi = 0; mi < 2; mi++) {
#pragma unroll
        for (int nt = 0; nt < 4; nt++) {
            float4 o = O[mi][nt];
            int r0 = b * 256 + qb + mi * 16 + gr;
            int col = h * 16 + nt * 4 + tg;
            g_att[(size_t)r0 * 96 + col] =
                pkh2(o.x * inv[mi][0], o.y * inv[mi][0]);
            g_att[(size_t)(r0 + 8) * 96 + col] =
                pkh2(o.z * inv[mi][1], o.w * inv[mi][1]);
        }
    }
}

// ---------------------------------------------------------------------------
// Launch
// ---------------------------------------------------------------------------
extern "C" void kernel_launch(void* const* d_in, const int* in_sizes, int n_in,
                              void* d_out, int out_size) {
    const float* x        = (const float*)d_in[0];
    const float* mask     = (const float*)d_in[1];
    const float* qkv_w    = (const float*)d_in[2];
    const float* qkv_b    = (const float*)d_in[3];
    const float* proj_w   = (const float*)d_in[4];
    const float* proj_b   = (const float*)d_in[5];
    const float* table    = (const float*)d_in[6];
    const int*   rel      = (const int*)d_in[7];
    float* out = (float*)d_out;

    cudaFuncSetAttribute(attn_f16_kernel,
                         cudaFuncAttributeMaxDynamicSharedMemorySize, 65536);
    cudaFuncSetAttribute(qkv_gemm_kernel,
                         cudaFuncAttributeMaxDynamicSharedMemorySize, GEMM_SMEM);
    cudaFuncSetAttribute(proj_gemm_kernel,
                         cudaFuncAttributeMaxDynamicSharedMemorySize, GEMM_SMEM);

    bias_gather_kernel<<<HEADS * NTOK * NTOK / 256, 256>>>(table, rel);
    qkv_gemm_kernel<<<dim3(2, ROWS / 128), 256, GEMM_SMEM>>>(x, qkv_w, qkv_b);
    attn_f16_kernel<<<dim3(HEADS, BATCH), 256, 65536>>>(mask);
    proj_gemm_kernel<<<dim3(2, ROWS / 128), 256, GEMM_SMEM>>>(proj_w, proj_b, out);
}